// round 6
// baseline (speedup 1.0000x reference)
#include <cuda_runtime.h>
#include <cstdint>

// Problem constants
#define BB 8
#define CC 3
#define HH 512
#define WW 512
#define KK 8

// Output layout (float32, concatenated in reference-return order):
//   best_warped [B,C,H,W], best_idx [B], best_mse [B],
//   all_warped  [B,K,C,H,W], all_mse [B,K], flows [K,H,W,2]
static constexpr size_t N_BW      = (size_t)BB * CC * HH * WW;          // 6,291,456
static constexpr size_t OFF_BW    = 0;
static constexpr size_t OFF_IDX   = N_BW;
static constexpr size_t OFF_BMSE  = OFF_IDX + BB;
static constexpr size_t OFF_AW    = OFF_BMSE + BB;                      // 6,291,472 (div by 4)
static constexpr size_t N_AW      = (size_t)BB * KK * CC * HH * WW;     // 50,331,648
static constexpr size_t OFF_AMSE  = OFF_AW + N_AW;
static constexpr size_t OFF_FLOWS = OFF_AMSE + (size_t)BB * KK;         // 56,623,184 (div by 4)

static constexpr int    ROW_F4    = WW / 4;                             // 128
static constexpr size_t CH_F4     = (size_t)HH * WW / 4;                // 65,536

// Scratch (no allocations allowed)
__device__ double g_mse[BB * KK];
__device__ __align__(16) float g_dx[KK * HH];  // dx[k][y]
__device__ __align__(16) float g_dy[KK * WW];  // dy[k][x]

__device__ __forceinline__ float softplusf(float v) {
    return v > 20.f ? v : log1pf(expf(v));
}

// ---------------------------------------------------------------------------
// Kernel 1: class params -> separable flow tables; zero MSE accumulators.
// ---------------------------------------------------------------------------
__global__ void prep_kernel(const float* __restrict__ cp) {
    __shared__ float su[KK], sv[KK], sdecx[KK], sdecy[KK];
    int tid = threadIdx.x;
    if (tid < KK) {
        sv[tid]    = 0.5f * tanhf(cp[4 * tid + 0]);   // v_left
        su[tid]    = 0.5f * tanhf(cp[4 * tid + 1]);   // u_top
        sdecx[tid] = softplusf(cp[4 * tid + 2]);      // decay_x
        sdecy[tid] = softplusf(cp[4 * tid + 3]);      // decay_y
    }
    __syncthreads();
    int g = blockIdx.x * 512 + tid;
    const float inv = 1.0f / 511.0f;
    if (g < KK * HH) {
        int k = g >> 9, y = g & 511;
        g_dx[g] = su[k] * expf(-sdecy[k] * ((float)y * inv));
    } else {
        int g2 = g - KK * HH;
        int k = g2 >> 9, x = g2 & 511;
        g_dy[g2] = sv[k] * expf(-sdecx[k] * ((float)x * inv));
    }
    if (blockIdx.x == 0 && tid < BB * KK) g_mse[tid] = 0.0;
}

// ---------------------------------------------------------------------------
// Per-class bilinear body. DELTA = uniform x-shift (0 or -1). STORE=false:
// return sum of squared error vs gr (MSE pass). STORE=true: streaming-store
// the warped row to out4+base4 (+ optionally best_warped at bwbase).
// Edge-replicated halo makes the uniform-wx lerp EXACT under border clamp.
// ---------------------------------------------------------------------------
template <int DELTA, bool STORE>
__device__ __forceinline__ float process_k(
    const float4 (&own)[CC][3], const float (&lv)[CC][3], const float (&rv)[CC][3],
    const float4 (&gr)[CC], float wx, float4 dy4,
    float4* __restrict__ out4, size_t base4, bool dobw, size_t bwbase)
{
    float dys0 = dy4.x, dys1 = dy4.y, dys2 = dy4.z, dys3 = dy4.w;
    bool  n0 = dys0 < 0.f, n1 = dys1 < 0.f, n2 = dys2 < 0.f, n3 = dys3 < 0.f;
    float wy0 = n0 ? dys0 + 1.f : dys0;
    float wy1 = n1 ? dys1 + 1.f : dys1;
    float wy2 = n2 ? dys2 + 1.f : dys2;
    float wy3 = n3 ? dys3 + 1.f : dys3;

    float acc = 0.f;
#pragma unroll
    for (int c = 0; c < CC; c++) {
        float xi[3][4];
#pragma unroll
        for (int r = 0; r < 3; r++) {
            float4 o = own[c][r];
            float e0, e1, e2, e3, f0, f1, f2, f3;
            if (DELTA == 0) {
                e0 = o.x; e1 = o.y; e2 = o.z; e3 = o.w;
                f0 = o.y; f1 = o.z; f2 = o.w; f3 = rv[c][r];
            } else {
                e0 = lv[c][r]; e1 = o.x; e2 = o.y; e3 = o.z;
                f0 = o.x;      f1 = o.y; f2 = o.z; f3 = o.w;
            }
            xi[r][0] = fmaf(wx, f0 - e0, e0);
            xi[r][1] = fmaf(wx, f1 - e1, e1);
            xi[r][2] = fmaf(wx, f2 - e2, e2);
            xi[r][3] = fmaf(wx, f3 - e3, e3);
        }
        float a0 = n0 ? xi[0][0] : xi[1][0], b0 = n0 ? xi[1][0] : xi[2][0];
        float a1 = n1 ? xi[0][1] : xi[1][1], b1 = n1 ? xi[1][1] : xi[2][1];
        float a2 = n2 ? xi[0][2] : xi[1][2], b2 = n2 ? xi[1][2] : xi[2][2];
        float a3 = n3 ? xi[0][3] : xi[1][3], b3 = n3 ? xi[1][3] : xi[2][3];
        float v0 = fmaf(wy0, b0 - a0, a0);
        float v1 = fmaf(wy1, b1 - a1, a1);
        float v2 = fmaf(wy2, b2 - a2, a2);
        float v3 = fmaf(wy3, b3 - a3, a3);
        if (STORE) {
            float4 v = make_float4(v0, v1, v2, v3);
            __stcs(out4 + base4 + (size_t)c * CH_F4, v);
            if (dobw) __stcs(out4 + bwbase + (size_t)c * CH_F4, v);
        } else {
            float d0 = v0 - gr[c].x, d1 = v1 - gr[c].y;
            float d2 = v2 - gr[c].z, d3 = v3 - gr[c].w;
            acc = fmaf(d0, d0, acc); acc = fmaf(d1, d1, acc);
            acc = fmaf(d2, d2, acc); acc = fmaf(d3, d3, acc);
        }
    }
    return acc;
}

// Shared loader: 3 clamped rows x 3 channels into registers + x-halo via smem.
__device__ __forceinline__ void load_window(
    const float* __restrict__ pred, int b, int y, int t,
    float4 (&own)[CC][3], float (&lv)[CC][3], float (&rv)[CC][3],
    float (*sLast)[3][128], float (*sFirst)[3][128])
{
    int ym1 = max(y - 1, 0);
    int yp1 = min(y + 1, HH - 1);
    const float4* pred4 = reinterpret_cast<const float4*>(pred);
#pragma unroll
    for (int c = 0; c < CC; c++) {
        size_t base = (size_t)(b * CC + c) * (HH * ROW_F4);
        own[c][0] = __ldg(&pred4[base + (size_t)ym1 * ROW_F4 + t]);
        own[c][1] = __ldg(&pred4[base + (size_t)y   * ROW_F4 + t]);
        own[c][2] = __ldg(&pred4[base + (size_t)yp1 * ROW_F4 + t]);
#pragma unroll
        for (int r = 0; r < 3; r++) {
            sLast [c][r][t] = own[c][r].w;
            sFirst[c][r][t] = own[c][r].x;
        }
    }
    __syncthreads();
#pragma unroll
    for (int c = 0; c < CC; c++)
#pragma unroll
        for (int r = 0; r < 3; r++) {
            lv[c][r] = (t > 0)   ? sLast [c][r][t - 1] : own[c][r].x;
            rv[c][r] = (t < 127) ? sFirst[c][r][t + 1] : own[c][r].w;
        }
}

// ---------------------------------------------------------------------------
// Kernel 2 (pass 1): MSE only. No global stores. grid = B*H x 128.
// ---------------------------------------------------------------------------
__global__ void __launch_bounds__(128)
mse_kernel(const float* __restrict__ pred, const float* __restrict__ gt) {
    __shared__ float sLast[CC][3][128];
    __shared__ float sFirst[CC][3][128];
    __shared__ float sred[4][KK];

    int bid = blockIdx.x;
    int b = bid >> 9;
    int y = bid & 511;
    int t = threadIdx.x;

    float4 own[CC][3], gr[CC];
    float lv[CC][3], rv[CC][3];
    const float4* gt4 = reinterpret_cast<const float4*>(gt);
#pragma unroll
    for (int c = 0; c < CC; c++)
        gr[c] = __ldg(&gt4[(size_t)(b * CC + c) * (HH * ROW_F4) + (size_t)y * ROW_F4 + t]);
    load_window(pred, b, y, t, own, lv, rv, sLast, sFirst);

    const float4* gdy4 = reinterpret_cast<const float4*>(g_dy);
    int lane = t & 31, warp = t >> 5;

#pragma unroll 1
    for (int k = 0; k < KK; k++) {
        float dxk = g_dx[(k << 9) + y];
        float4 dy4 = __ldg(&gdy4[k * 128 + t]);
        bool neg = dxk < 0.f;
        float wx = neg ? dxk + 1.f : dxk;
        float acc = neg
            ? process_k<-1, false>(own, lv, rv, gr, wx, dy4, nullptr, 0, false, 0)
            : process_k< 0, false>(own, lv, rv, gr, wx, dy4, nullptr, 0, false, 0);
#pragma unroll
        for (int off = 16; off > 0; off >>= 1)
            acc += __shfl_down_sync(0xffffffffu, acc, off);
        if (lane == 0) sred[warp][k] = acc;
    }
    __syncthreads();
    if (t < KK) {
        double s = 0.0;
#pragma unroll
        for (int w = 0; w < 4; w++) s += (double)sred[w][t];
        atomicAdd(&g_mse[b * KK + t], s);
    }
}

// ---------------------------------------------------------------------------
// Kernel 3 (pass 2): write all_warped (+ dual-store best_warped when k is the
// argmin), flows rows, and scalar outputs. grid = (B+K)*H x 128.
// ---------------------------------------------------------------------------
__global__ void __launch_bounds__(128)
write_kernel(const float* __restrict__ pred, float* __restrict__ out) {
    __shared__ float sLast[CC][3][128];
    __shared__ float sFirst[CC][3][128];

    int bid = blockIdx.x;
    int t = threadIdx.x;
    float4* out4 = reinterpret_cast<float4*>(out);

    if (bid >= BB * HH) {                 // ---- flows + scalar-output blocks ----
        int fid = bid - BB * HH;          // k*H + y
        int k = fid >> 9;
        float dxv = g_dx[fid];
        const float4* gdy4 = reinterpret_cast<const float4*>(g_dy);
        float4 dy4 = __ldg(&gdy4[k * 128 + t]);
        size_t f4 = OFF_FLOWS / 4 + (size_t)fid * 256 + 2 * t;
        __stcs(out4 + f4,     make_float4(dxv, dy4.x, dxv, dy4.y));
        __stcs(out4 + f4 + 1, make_float4(dxv, dy4.z, dxv, dy4.w));
        if (fid == 0) {                   // fold former reduce_kernel in here
            const double invN = 1.0 / ((double)CC * HH * WW);
            if (t < BB * KK)
                out[OFF_AMSE + t] = (float)(g_mse[t] * invN);
            if (t < BB) {
                double best = g_mse[t * KK];
                int bi = 0;
#pragma unroll
                for (int k2 = 1; k2 < KK; k2++) {
                    double v = g_mse[t * KK + k2];
                    if (v < best) { best = v; bi = k2; }   // first-min = jnp.argmin
                }
                out[OFF_IDX  + t] = (float)bi;
                out[OFF_BMSE + t] = (float)(best * invN);
            }
        }
        return;
    }

    int b = bid >> 9;
    int y = bid & 511;

    // inline argmin (same strict-< tie-break everywhere)
    double best = g_mse[b * KK];
    int bestk = 0;
#pragma unroll
    for (int j = 1; j < KK; j++) {
        double v = g_mse[b * KK + j];
        if (v < best) { best = v; bestk = j; }
    }

    float4 own[CC][3], grdummy[CC];
    float lv[CC][3], rv[CC][3];
    load_window(pred, b, y, t, own, lv, rv, sLast, sFirst);

    const float4* gdy4 = reinterpret_cast<const float4*>(g_dy);
    size_t bwbase = OFF_BW / 4 + ((size_t)(b * CC) * HH + (size_t)y) * ROW_F4 + t;

#pragma unroll 1
    for (int k = 0; k < KK; k++) {
        float dxk = g_dx[(k << 9) + y];
        float4 dy4 = __ldg(&gdy4[k * 128 + t]);
        size_t base4 = OFF_AW / 4 +
                       ((size_t)((b * KK + k) * CC) * HH + (size_t)y) * ROW_F4 + t;
        bool neg = dxk < 0.f;
        float wx = neg ? dxk + 1.f : dxk;
        bool dobw = (k == bestk);
        if (neg)
            process_k<-1, true>(own, lv, rv, grdummy, wx, dy4, out4, base4, dobw, bwbase);
        else
            process_k< 0, true>(own, lv, rv, grdummy, wx, dy4, out4, base4, dobw, bwbase);
    }
}

// ---------------------------------------------------------------------------
extern "C" void kernel_launch(void* const* d_in, const int* in_sizes, int n_in,
                              void* d_out, int out_size) {
    const float* pred = (const float*)d_in[0];   // [B,C,H,W]
    const float* gt   = (const float*)d_in[1];   // [B,C,H,W]
    const float* cp   = (const float*)d_in[2];   // [K,4]
    float* out = (float*)d_out;

    prep_kernel<<<16, 512>>>(cp);
    mse_kernel<<<BB * HH, 128>>>(pred, gt);
    write_kernel<<<(BB + KK) * HH, 128>>>(pred, out);
}

// round 7
// speedup vs baseline: 1.2861x; 1.2861x over previous
#include <cuda_runtime.h>
#include <cstdint>

// Problem constants
#define BB 8
#define CC 3
#define HH 512
#define WW 512
#define KK 8

// Output layout (float32, concatenated in reference-return order):
//   best_warped [B,C,H,W], best_idx [B], best_mse [B],
//   all_warped  [B,K,C,H,W], all_mse [B,K], flows [K,H,W,2]
static constexpr size_t N_BW      = (size_t)BB * CC * HH * WW;          // 6,291,456
static constexpr size_t OFF_BW    = 0;
static constexpr size_t OFF_IDX   = N_BW;
static constexpr size_t OFF_BMSE  = OFF_IDX + BB;
static constexpr size_t OFF_AW    = OFF_BMSE + BB;                      // 6,291,472 (div by 4)
static constexpr size_t N_AW      = (size_t)BB * KK * CC * HH * WW;     // 50,331,648
static constexpr size_t OFF_AMSE  = OFF_AW + N_AW;
static constexpr size_t OFF_FLOWS = OFF_AMSE + (size_t)BB * KK;         // 56,623,184 (div by 4)

static constexpr size_t IMG_F4    = (size_t)CC * HH * WW / 4;           // 196,608 float4 per image
static constexpr int    ROW_F4    = WW / 4;                             // 128

// Scratch (no allocations allowed)
__device__ double g_mse[BB * KK];
__device__ __align__(16) float g_dx[KK * HH];  // dx[k][y]
__device__ __align__(16) float g_dy[KK * WW];  // dy[k][x]

__device__ __forceinline__ float softplusf(float v) {
    return v > 20.f ? v : log1pf(expf(v));
}

// ---------------------------------------------------------------------------
// Kernel 1: class params -> separable flow tables; zero MSE accumulators.
// ---------------------------------------------------------------------------
__global__ void prep_kernel(const float* __restrict__ cp) {
    __shared__ float su[KK], sv[KK], sdecx[KK], sdecy[KK];
    int tid = threadIdx.x;
    if (tid < KK) {
        sv[tid]    = 0.5f * tanhf(cp[4 * tid + 0]);   // v_left
        su[tid]    = 0.5f * tanhf(cp[4 * tid + 1]);   // u_top
        sdecx[tid] = softplusf(cp[4 * tid + 2]);      // decay_x
        sdecy[tid] = softplusf(cp[4 * tid + 3]);      // decay_y
    }
    __syncthreads();
    int g = blockIdx.x * 512 + tid;
    const float inv = 1.0f / 511.0f;
    if (g < KK * HH) {
        int k = g >> 9, y = g & 511;
        g_dx[g] = su[k] * expf(-sdecy[k] * ((float)y * inv));
    } else {
        int g2 = g - KK * HH;
        int k = g2 >> 9, x = g2 & 511;
        g_dy[g2] = sv[k] * expf(-sdecx[k] * ((float)x * inv));
    }
    if (blockIdx.x == 0 && tid < BB * KK) g_mse[tid] = 0.0;
}

// ---------------------------------------------------------------------------
// Per-class body for the hot kernel. DELTA is the (uniform per block,k)
// x-shift: 0 if dxk >= 0, -1 if dxk < 0. Edge-replicated halo makes the
// uniform-wx lerp EXACT under border-clamp semantics at x=0 / x=511.
// ---------------------------------------------------------------------------
template <int DELTA>
__device__ __forceinline__ float process_k(
    const float4 (&own)[CC][3], const float (&lv)[CC][3], const float (&rv)[CC][3],
    const float4 (&gr)[CC], float wx, float4 dy4,
    float4* __restrict__ out4, size_t base4)
{
    float dys0 = dy4.x, dys1 = dy4.y, dys2 = dy4.z, dys3 = dy4.w;
    bool  n0 = dys0 < 0.f, n1 = dys1 < 0.f, n2 = dys2 < 0.f, n3 = dys3 < 0.f;
    float wy0 = n0 ? dys0 + 1.f : dys0;
    float wy1 = n1 ? dys1 + 1.f : dys1;
    float wy2 = n2 ? dys2 + 1.f : dys2;
    float wy3 = n3 ? dys3 + 1.f : dys3;

    float acc = 0.f;
#pragma unroll
    for (int c = 0; c < CC; c++) {
        float xi[3][4];
#pragma unroll
        for (int r = 0; r < 3; r++) {
            float4 o = own[c][r];
            float e0, e1, e2, e3, f0, f1, f2, f3;
            if (DELTA == 0) {
                e0 = o.x; e1 = o.y; e2 = o.z; e3 = o.w;
                f0 = o.y; f1 = o.z; f2 = o.w; f3 = rv[c][r];
            } else {
                e0 = lv[c][r]; e1 = o.x; e2 = o.y; e3 = o.z;
                f0 = o.x;      f1 = o.y; f2 = o.z; f3 = o.w;
            }
            xi[r][0] = fmaf(wx, f0 - e0, e0);
            xi[r][1] = fmaf(wx, f1 - e1, e1);
            xi[r][2] = fmaf(wx, f2 - e2, e2);
            xi[r][3] = fmaf(wx, f3 - e3, e3);
        }
        // y-lerp with per-pixel row select (edge replication via clamped rows)
        float a0 = n0 ? xi[0][0] : xi[1][0], b0 = n0 ? xi[1][0] : xi[2][0];
        float a1 = n1 ? xi[0][1] : xi[1][1], b1 = n1 ? xi[1][1] : xi[2][1];
        float a2 = n2 ? xi[0][2] : xi[1][2], b2 = n2 ? xi[1][2] : xi[2][2];
        float a3 = n3 ? xi[0][3] : xi[1][3], b3 = n3 ? xi[1][3] : xi[2][3];
        float v0 = fmaf(wy0, b0 - a0, a0);
        float v1 = fmaf(wy1, b1 - a1, a1);
        float v2 = fmaf(wy2, b2 - a2, a2);
        float v3 = fmaf(wy3, b3 - a3, a3);
        __stcs(out4 + base4 + (size_t)c * (HH * WW / 4),
               make_float4(v0, v1, v2, v3));
        float d0 = v0 - gr[c].x, d1 = v1 - gr[c].y;
        float d2 = v2 - gr[c].z, d3 = v3 - gr[c].w;
        acc = fmaf(d0, d0, acc); acc = fmaf(d1, d1, acc);
        acc = fmaf(d2, d2, acc); acc = fmaf(d3, d3, acc);
    }
    return acc;
}

// ---------------------------------------------------------------------------
// Kernel 2 (hot): blocks [0, B*H): one (b,y) row, 128 threads x 4 px each.
// Blocks [B*H, B*H+K*H): emit flows row. grid = (B+K)*H x 128.
// ---------------------------------------------------------------------------
__global__ void __launch_bounds__(128)
warp_mse_kernel(const float* __restrict__ pred, const float* __restrict__ gt,
                float* __restrict__ out) {
    __shared__ float sLast[CC][3][128];   // own.w per thread  (value at 4t+3)
    __shared__ float sFirst[CC][3][128];  // own.x per thread  (value at 4t)
    __shared__ float sred[4][KK];

    int bid = blockIdx.x;
    int t = threadIdx.x;
    float4* out4 = reinterpret_cast<float4*>(out);

    if (bid >= BB * HH) {                 // ---- fused flows blocks ----
        int fid = bid - BB * HH;          // k*H + y
        int k = fid >> 9;
        float dxv = g_dx[fid];
        const float4* gdy4 = reinterpret_cast<const float4*>(g_dy);
        float4 dy4 = __ldg(&gdy4[k * 128 + t]);
        size_t f4 = OFF_FLOWS / 4 + (size_t)fid * 256 + 2 * t;  // 2 float4 per thread
        __stcs(out4 + f4,     make_float4(dxv, dy4.x, dxv, dy4.y));
        __stcs(out4 + f4 + 1, make_float4(dxv, dy4.z, dxv, dy4.w));
        return;
    }

    int b = bid >> 9;
    int y = bid & 511;
    int ym1 = max(y - 1, 0);
    int yp1 = min(y + 1, HH - 1);

    float4 own[CC][3];
    float4 gr[CC];
    const float4* pred4 = reinterpret_cast<const float4*>(pred);
    const float4* gt4   = reinterpret_cast<const float4*>(gt);
#pragma unroll
    for (int c = 0; c < CC; c++) {
        size_t base = (size_t)(b * CC + c) * (HH * ROW_F4);
        own[c][0] = __ldg(&pred4[base + (size_t)ym1 * ROW_F4 + t]);
        own[c][1] = __ldg(&pred4[base + (size_t)y   * ROW_F4 + t]);
        own[c][2] = __ldg(&pred4[base + (size_t)yp1 * ROW_F4 + t]);
        gr[c]     = __ldg(&gt4  [base + (size_t)y   * ROW_F4 + t]);
#pragma unroll
        for (int r = 0; r < 3; r++) {
            sLast [c][r][t] = own[c][r].w;
            sFirst[c][r][t] = own[c][r].x;
        }
    }
    __syncthreads();

    // Halo with edge replication (v[-1]:=v[0], v[512]:=v[511]); hoisted out of k loop.
    float lv[CC][3], rv[CC][3];
#pragma unroll
    for (int c = 0; c < CC; c++)
#pragma unroll
        for (int r = 0; r < 3; r++) {
            lv[c][r] = (t > 0)   ? sLast [c][r][t - 1] : own[c][r].x;
            rv[c][r] = (t < 127) ? sFirst[c][r][t + 1] : own[c][r].w;
        }

    const float4* gdy4 = reinterpret_cast<const float4*>(g_dy);
    int lane = t & 31, warp = t >> 5;

#pragma unroll 1
    for (int k = 0; k < KK; k++) {
        float dxk = g_dx[(k << 9) + y];                 // uniform per block
        float4 dy4 = __ldg(&gdy4[k * 128 + t]);
        size_t base4 = OFF_AW / 4 +
                       ((size_t)((b * KK + k) * CC) * HH + (size_t)y) * ROW_F4 + t;
        bool neg = dxk < 0.f;
        float wx = neg ? dxk + 1.f : dxk;
        float acc = neg
            ? process_k<-1>(own, lv, rv, gr, wx, dy4, out4, base4)
            : process_k< 0>(own, lv, rv, gr, wx, dy4, out4, base4);
#pragma unroll
        for (int off = 16; off > 0; off >>= 1)
            acc += __shfl_down_sync(0xffffffffu, acc, off);
        if (lane == 0) sred[warp][k] = acc;
    }
    __syncthreads();
    if (t < KK) {
        double s = 0.0;
#pragma unroll
        for (int w = 0; w < 4; w++) s += (double)sred[w][t];
        atomicAdd(&g_mse[b * KK + t], s);
    }
}

// ---------------------------------------------------------------------------
// Kernel 3: gather (MLP=8 streaming copy of winning slice) + folded reduce.
// grid = B*96 + 1 blocks x 256 threads. Each copy block moves 2048 float4
// (8 per thread, 256-stride for coalescing + MLP). Last block writes the
// scalar outputs (all_mse, best_idx, best_mse).
// ---------------------------------------------------------------------------
__global__ void __launch_bounds__(256)
gather_kernel(float* __restrict__ out) {
    int bid = blockIdx.x;
    int t = threadIdx.x;

    if (bid == BB * 96) {                 // ---- folded reduce block ----
        const double invN = 1.0 / ((double)CC * HH * WW);
        if (t < BB * KK)
            out[OFF_AMSE + t] = (float)(g_mse[t] * invN);
        if (t < BB) {
            double best = g_mse[t * KK];
            int bi = 0;
#pragma unroll
            for (int k = 1; k < KK; k++) {
                double v = g_mse[t * KK + k];
                if (v < best) { best = v; bi = k; }   // first-min = jnp.argmin
            }
            out[OFF_IDX  + t] = (float)bi;
            out[OFF_BMSE + t] = (float)(best * invN);
        }
        return;
    }

    int b = bid / 96;
    int blk = bid - b * 96;

    // inline argmin (identical tie-break to the reduce block)
    double best = g_mse[b * KK];
    int k = 0;
#pragma unroll
    for (int j = 1; j < KK; j++) {
        double v = g_mse[b * KK + j];
        if (v < best) { best = v; k = j; }
    }

    size_t idx = (size_t)blk * 2048 + t;
    const float4* src = reinterpret_cast<const float4*>(out) + OFF_AW / 4 +
                        (size_t)(b * KK + k) * IMG_F4 + idx;
    float4* dst = reinterpret_cast<float4*>(out) + (size_t)b * IMG_F4 + idx;
    float4 v0 = __ldcs(src);
    float4 v1 = __ldcs(src + 256);
    float4 v2 = __ldcs(src + 512);
    float4 v3 = __ldcs(src + 768);
    float4 v4 = __ldcs(src + 1024);
    float4 v5 = __ldcs(src + 1280);
    float4 v6 = __ldcs(src + 1536);
    float4 v7 = __ldcs(src + 1792);
    __stcs(dst,        v0);
    __stcs(dst + 256,  v1);
    __stcs(dst + 512,  v2);
    __stcs(dst + 768,  v3);
    __stcs(dst + 1024, v4);
    __stcs(dst + 1280, v5);
    __stcs(dst + 1536, v6);
    __stcs(dst + 1792, v7);
}

// ---------------------------------------------------------------------------
extern "C" void kernel_launch(void* const* d_in, const int* in_sizes, int n_in,
                              void* d_out, int out_size) {
    const float* pred = (const float*)d_in[0];   // [B,C,H,W]
    const float* gt   = (const float*)d_in[1];   // [B,C,H,W]
    const float* cp   = (const float*)d_in[2];   // [K,4]
    float* out = (float*)d_out;

    prep_kernel<<<16, 512>>>(cp);
    warp_mse_kernel<<<(BB + KK) * HH, 128>>>(pred, gt, out);
    gather_kernel<<<BB * 96 + 1, 256>>>(out);
}